// round 7
// baseline (speedup 1.0000x reference)
#include <cuda_runtime.h>
#include <math.h>
#include <stdint.h>

// Problem constants (fixed shapes)
#define BB    512
#define NN    64
#define NFG   1024
#define NFR   256
#define MTOT  (BB * NN)                          // 32768
#define OUT_ELEMS  ((size_t)MTOT * NFG)          // 33554432
#define REL_ELEMS  ((size_t)BB * NN * NN)        // 2097152

// Scratch (device globals — allocation-free)
__device__ float g_tp[(size_t)MTOT * 512];       // theta (cols 0..255) | phi (256..511)
__device__ float g_agg[(size_t)MTOT * NFG];      // relation @ feats (tf32-rounded)
__device__ float g_rel[REL_ELEMS];               // fallback relation scratch
__device__ float g_wtp[(size_t)512 * 1024];      // [N=512][K=1024] = [WthT;WphT], tf32-rounded
__device__ float g_wg[(size_t)1024 * 1024];      // WgT [N][K], tf32-rounded
__device__ float g_bias[512];                    // concat(b_theta, b_phi)

// ---------------------------------------------------------------------------
// Helpers (all compute_80-era PTX or older — legal at compute_103)
// ---------------------------------------------------------------------------
__device__ __forceinline__ uint32_t smem_u32(const void* p) {
    uint32_t a;
    asm("{ .reg .u64 t; cvta.to.shared.u64 t, %1; cvt.u32.u64 %0, t; }" : "=r"(a) : "l"(p));
    return a;
}
__device__ __forceinline__ float rna_tf32(float x) {
    uint32_t r;
    asm("cvt.rna.tf32.f32 %0, %1;" : "=r"(r) : "f"(x));
    return __uint_as_float(r);
}
__device__ __forceinline__ void cp_async16(uint32_t dst, const void* src) {
    asm volatile("cp.async.cg.shared.global [%0], [%1], 16;" :: "r"(dst), "l"(src));
}
#define CP_COMMIT() asm volatile("cp.async.commit_group;" ::: "memory")
#define CP_WAIT1()  asm volatile("cp.async.wait_group 1;" ::: "memory")

__device__ __forceinline__ void ldsm_x4(uint32_t& r0, uint32_t& r1,
                                        uint32_t& r2, uint32_t& r3, uint32_t addr) {
    asm volatile("ldmatrix.sync.aligned.m8n8.x4.shared.b16 {%0,%1,%2,%3}, [%4];"
                 : "=r"(r0), "=r"(r1), "=r"(r2), "=r"(r3) : "r"(addr));
}

__device__ __forceinline__ void mma_tf32(float& d0, float& d1, float& d2, float& d3,
                                         uint32_t a0, uint32_t a1, uint32_t a2, uint32_t a3,
                                         uint32_t b0, uint32_t b1) {
    asm volatile(
        "mma.sync.aligned.m16n8k8.row.col.f32.tf32.tf32.f32 "
        "{%0,%1,%2,%3}, {%4,%5,%6,%7}, {%8,%9}, {%0,%1,%2,%3};"
        : "+f"(d0), "+f"(d1), "+f"(d2), "+f"(d3)
        : "r"(a0), "r"(a1), "r"(a2), "r"(a3), "r"(b0), "r"(b1));
}

// ---------------------------------------------------------------------------
// Prologue: weight transpose + tf32 rounding: dst[N][K] = rna(src[K][N]),
// and bias concat.
// ---------------------------------------------------------------------------
__global__ void transpose_rna_kernel(const float* __restrict__ src,
                                     float* __restrict__ dst, int K, int N)
{
    __shared__ float tile[32][33];
    const int n0 = blockIdx.x * 32, k0 = blockIdx.y * 32;
    const int tx = threadIdx.x, ty = threadIdx.y;   // 32 x 8
#pragma unroll
    for (int r = 0; r < 32; r += 8)
        tile[ty + r][tx] = src[(size_t)(k0 + ty + r) * N + n0 + tx];
    __syncthreads();
#pragma unroll
    for (int r = 0; r < 32; r += 8)
        dst[(size_t)(n0 + ty + r) * K + k0 + tx] = rna_tf32(tile[tx][ty + r]);
}

__global__ void bias_concat_kernel(const float* __restrict__ bth,
                                   const float* __restrict__ bph,
                                   float* __restrict__ bias)
{
    int i = threadIdx.x;
    bias[i] = (i < 256) ? bth[i] : bph[i - 256];
}

// ---------------------------------------------------------------------------
// tf32 mma.sync GEMM, ldmatrix fragments, fragment double-buffering.
// C[M,N] = op(A[M,K] @ Bt[N,K]^T) (+bias) (relu)
// CTA 128x128, BK=32, 3-stage cp.async, 256 threads (8 warps 2x4,
// warp tile 64x32, 4x4 m16n8k8 per k-step), 2 CTAs/SM (reg-capped 128).
// Smem tile layout (A and B): [row][32 k-floats], 128B rows, 16B chunk
// XOR-swizzled with (row&7) -> conflict-free ldmatrix & stores.
// Bt pre-rounded to tf32; A consumed raw (HMMA truncation, ~6e-5 rel bias).
// Requires M%128==0, N%128==0, K%32==0.
// ---------------------------------------------------------------------------
#define STAGE_BYTES 32768u                 // A 16KB + B 16KB
#define GEMM_SMEM   (3 * 32768)            // 98304 bytes -> 2 CTAs/SM

template <int RELU, int HASBIAS>
__global__ void __launch_bounds__(256, 2) gemm_tf32(
    const float* __restrict__ A, int lda,
    const float* __restrict__ Bt, int ldb,
    const float* __restrict__ bias,
    float* __restrict__ C, int ldc, int K)
{
    extern __shared__ float sm[];
    const uint32_t smBase = smem_u32(sm);

    const int tid = threadIdx.x;
    const int bm = blockIdx.y * 128;
    const int bn = blockIdx.x * 128;

    const int wid  = tid >> 5;
    const int lane = tid & 31;
    const int g = lane >> 2;                // MMA groupID
    const int t = lane & 3;                 // MMA threadID_in_group
    const int warp_m = (wid & 1) * 64;
    const int warp_n = (wid >> 1) * 32;

    // Precomputed ldmatrix address components.
    // addr = sb + rowBase + ((chunk<<4) ^ rowX), chunk = ks*2 + sel
    uint32_t aBase[4], aX[4];
#pragma unroll
    for (int mt = 0; mt < 4; ++mt) {
        const int row = warp_m + mt * 16 + (lane & 7) + ((lane >> 3) & 1) * 8;
        aBase[mt] = (uint32_t)(row * 128);
        aX[mt] = (uint32_t)((row & 7) << 4);
    }
    const int aCsel = lane >> 4;
    uint32_t bBase[2], bX[2];
#pragma unroll
    for (int p = 0; p < 2; ++p) {
        const int row = warp_n + (2 * p + ((lane >> 4) & 1)) * 8 + (lane & 7);
        bBase[p] = 16384u + (uint32_t)(row * 128);
        bX[p] = (uint32_t)((row & 7) << 4);
    }
    const int bCsel = (lane >> 3) & 1;

    // stage one BK=32 chunk into buffer s (8 x cp.async 16B per thread)
    auto stage = [&](int kc, int s) {
        const int k0 = kc * 32;
        const uint32_t base = smBase + (uint32_t)s * STAGE_BYTES;
#pragma unroll
        for (int r = 0; r < 4; ++r) {
            int idx = tid + 256 * r;               // 0..1023
            int row = idx >> 3, c = idx & 7;
            uint32_t dst = base + (uint32_t)(row * 128 + ((c ^ (row & 7)) << 4));
            cp_async16(dst, A + (size_t)(bm + row) * lda + k0 + c * 4);
        }
#pragma unroll
        for (int r = 0; r < 4; ++r) {
            int idx = tid + 256 * r;
            int row = idx >> 3, c = idx & 7;
            uint32_t dst = base + 16384u + (uint32_t)(row * 128 + ((c ^ (row & 7)) << 4));
            cp_async16(dst, Bt + (size_t)(bn + row) * ldb + k0 + c * 4);
        }
    };

    float acc[4][4][4];
#pragma unroll
    for (int mt = 0; mt < 4; ++mt)
#pragma unroll
        for (int nt = 0; nt < 4; ++nt)
#pragma unroll
            for (int q = 0; q < 4; ++q) acc[mt][nt][q] = 0.f;

    const int NC = K / 32;
    stage(0, 0); CP_COMMIT();
    stage(1, 1); CP_COMMIT();

    uint32_t a[2][4][4], b[2][4][2];

    for (int i = 0; i < NC; ++i) {
        CP_WAIT1();               // this thread's copies of chunk i done
        __syncthreads();          // all threads' copies visible; buf (i+2)%3 free
        if (i + 2 < NC) stage(i + 2, (i + 2) % 3);
        CP_COMMIT();

        const uint32_t sb = smBase + (uint32_t)(i % 3) * STAGE_BYTES;

        // load k-step 0 fragments into slot 0
        {
            const uint32_t ca = (uint32_t)(aCsel << 4);
            const uint32_t cb = (uint32_t)(bCsel << 4);
#pragma unroll
            for (int mt = 0; mt < 4; ++mt)
                ldsm_x4(a[0][mt][0], a[0][mt][1], a[0][mt][2], a[0][mt][3],
                        sb + aBase[mt] + (ca ^ aX[mt]));
#pragma unroll
            for (int p = 0; p < 2; ++p)
                ldsm_x4(b[0][2 * p][0], b[0][2 * p][1], b[0][2 * p + 1][0], b[0][2 * p + 1][1],
                        sb + bBase[p] + (cb ^ bX[p]));
        }

#pragma unroll
        for (int ks = 0; ks < 4; ++ks) {
            const int cur = ks & 1;
            const int nxt = cur ^ 1;
            if (ks < 3) {          // prefetch k-step ks+1 while MMAs run on ks
                const uint32_t ca = (uint32_t)(((ks + 1) * 2 + aCsel) << 4);
                const uint32_t cb = (uint32_t)(((ks + 1) * 2 + bCsel) << 4);
#pragma unroll
                for (int mt = 0; mt < 4; ++mt)
                    ldsm_x4(a[nxt][mt][0], a[nxt][mt][1], a[nxt][mt][2], a[nxt][mt][3],
                            sb + aBase[mt] + (ca ^ aX[mt]));
#pragma unroll
                for (int p = 0; p < 2; ++p)
                    ldsm_x4(b[nxt][2 * p][0], b[nxt][2 * p][1],
                            b[nxt][2 * p + 1][0], b[nxt][2 * p + 1][1],
                            sb + bBase[p] + (cb ^ bX[p]));
            }
#pragma unroll
            for (int mt = 0; mt < 4; ++mt)
#pragma unroll
                for (int nt = 0; nt < 4; ++nt)
                    mma_tf32(acc[mt][nt][0], acc[mt][nt][1],
                             acc[mt][nt][2], acc[mt][nt][3],
                             a[cur][mt][0], a[cur][mt][1], a[cur][mt][2], a[cur][mt][3],
                             b[cur][nt][0], b[cur][nt][1]);
        }
    }

    // Epilogue: c0,c1 -> (row, col..col+1); c2,c3 -> (row+8, col..col+1)
#pragma unroll
    for (int mt = 0; mt < 4; ++mt) {
        const int row = bm + warp_m + mt * 16 + g;
#pragma unroll
        for (int nt = 0; nt < 4; ++nt) {
            const int col = bn + warp_n + nt * 8 + 2 * t;
            float v0 = acc[mt][nt][0], v1 = acc[mt][nt][1];
            float v2 = acc[mt][nt][2], v3 = acc[mt][nt][3];
            if (HASBIAS) {
                float b0 = bias[col], b1 = bias[col + 1];
                v0 += b0; v1 += b1; v2 += b0; v3 += b1;
            }
            if (RELU) {
                v0 = fmaxf(v0, 0.f); v1 = fmaxf(v1, 0.f);
                v2 = fmaxf(v2, 0.f); v3 = fmaxf(v3, 0.f);
            }
            *(float2*)(C + (size_t)row * ldc + col) = make_float2(v0, v1);
            *(float2*)(C + (size_t)(row + 8) * ldc + col) = make_float2(v2, v3);
        }
    }
}

// ---------------------------------------------------------------------------
// Per-batch: sim = theta @ phi^T / 16, positional mask, softmax over m.
// ---------------------------------------------------------------------------
__global__ void __launch_bounds__(256) sim_softmax_kernel(
    const float* __restrict__ boxes, float* __restrict__ rel)
{
    __shared__ float th_k[32][68];
    __shared__ float ph_k[32][68];
    __shared__ float sS[64 * 65];
    __shared__ float cx[64], cy[64];

    const int b = blockIdx.x;
    const int tid = threadIdx.x;

    if (tid < 64) {
        const float* bb = boxes + ((size_t)b * 64 + tid) * 4;
        cx[tid] = (bb[0] + bb[2]) * 0.5f;
        cy[tid] = (bb[1] + bb[3]) * 0.5f;
    }

    const float4* src4 = (const float4*)(g_tp + (size_t)b * 64 * 512);
    const int tn = (tid >> 4) << 2;
    const int tm = (tid & 15) << 2;

    float acc[4][4];
#pragma unroll
    for (int i = 0; i < 4; ++i)
#pragma unroll
        for (int j = 0; j < 4; ++j) acc[i][j] = 0.f;

    for (int kc = 0; kc < 256; kc += 32) {
        for (int i = tid; i < 512; i += 256) {
            int r = i >> 3;
            int c4 = i & 7;
            int k0 = c4 << 2;
            float4 v = src4[r * 128 + (kc >> 2) + c4];
            th_k[k0 + 0][r] = v.x; th_k[k0 + 1][r] = v.y;
            th_k[k0 + 2][r] = v.z; th_k[k0 + 3][r] = v.w;
            float4 w = src4[r * 128 + 64 + (kc >> 2) + c4];
            ph_k[k0 + 0][r] = w.x; ph_k[k0 + 1][r] = w.y;
            ph_k[k0 + 2][r] = w.z; ph_k[k0 + 3][r] = w.w;
        }
        __syncthreads();
#pragma unroll 8
        for (int k = 0; k < 32; ++k) {
            float a[4], p[4];
#pragma unroll
            for (int i = 0; i < 4; ++i) a[i] = th_k[k][tn + i];
#pragma unroll
            for (int j = 0; j < 4; ++j) p[j] = ph_k[k][tm + j];
#pragma unroll
            for (int i = 0; i < 4; ++i)
#pragma unroll
                for (int j = 0; j < 4; ++j)
                    acc[i][j] += a[i] * p[j];
        }
        __syncthreads();
    }

#pragma unroll
    for (int i = 0; i < 4; ++i)
#pragma unroll
        for (int j = 0; j < 4; ++j)
            sS[(tn + i) * 65 + tm + j] = acc[i][j] * 0.0625f;
    __syncthreads();

    if (tid < 64) {
        const int n = tid;
        const float cxn = cx[n], cyn = cy[n];
        const float thr = 0.2f * 157.0f;
        const float thr2 = thr * thr;
        float mx = -INFINITY;
        for (int m = 0; m < 64; ++m) {
            float dx = cxn - cx[m];
            float dy = cyn - cy[m];
            float d2 = dx * dx + dy * dy;
            float v = (d2 > thr2) ? -INFINITY : sS[n * 65 + m];
            sS[n * 65 + m] = v;
            mx = fmaxf(mx, v);
        }
        float s = 0.f;
        for (int m = 0; m < 64; ++m) {
            float e = expf(sS[n * 65 + m] - mx);
            sS[n * 65 + m] = e;
            s += e;
        }
        float inv = 1.f / s;
        for (int m = 0; m < 64; ++m)
            sS[n * 65 + m] *= inv;
    }
    __syncthreads();

    float* ro = rel + (size_t)b * 4096;
    for (int i = tid; i < 4096; i += 256)
        ro[i] = sS[(i >> 6) * 65 + (i & 63)];
}

// ---------------------------------------------------------------------------
// agg = relation[64,64] @ feats[64,1024], output tf32-rounded for GEMM2.
// ---------------------------------------------------------------------------
#define AGG_SMEM ((64 * 256 + 64 * 68) * 4)   // 82944

__global__ void __launch_bounds__(256) agg_kernel(
    const float* __restrict__ feats, const float* __restrict__ rel,
    float* __restrict__ agg)
{
    extern __shared__ float smA[];
    float* sfeats = smA;                 // [64][256]
    float* relT   = smA + 64 * 256;      // [64][68]

    const int b = blockIdx.x;
    const int fchunk = blockIdx.y * 256;
    const int tid = threadIdx.x;

    const float4* fsrc = (const float4*)(feats + (size_t)b * 64 * 1024 + fchunk);
#pragma unroll
    for (int r = 0; r < 16; ++r) {
        int idx = tid + 256 * r;        // 0..4095 float4s
        int m = idx >> 6, c4 = idx & 63;
        *(float4*)(sfeats + m * 256 + c4 * 4) = fsrc[(size_t)m * 256 + c4];
    }
    const float* rsrc = rel + (size_t)b * 4096;
#pragma unroll
    for (int r = 0; r < 16; ++r) {
        int idx = tid + 256 * r;
        int n = idx >> 6, m = idx & 63;
        relT[m * 68 + n] = rsrc[idx];
    }
    __syncthreads();

    const int fl = tid & 31;            // f-cols fl*4..+3 and 128+fl*4..+3
    const int ng = tid >> 5;            // n-rows ng*8..+7

    float acc[8][8];
#pragma unroll
    for (int i = 0; i < 8; ++i)
#pragma unroll
        for (int j = 0; j < 8; ++j) acc[i][j] = 0.f;

    const float* f0p = sfeats + fl * 4;
    const float* f1p = sfeats + 128 + fl * 4;
    const float* rp  = relT + ng * 8;

#pragma unroll 4
    for (int m = 0; m < 64; ++m) {
        float4 fa = *(const float4*)(f0p + m * 256);
        float4 fb = *(const float4*)(f1p + m * 256);
        float4 ra = *(const float4*)(rp + m * 68);
        float4 rb = *(const float4*)(rp + m * 68 + 4);
        float fv[8] = {fa.x, fa.y, fa.z, fa.w, fb.x, fb.y, fb.z, fb.w};
        float rv[8] = {ra.x, ra.y, ra.z, ra.w, rb.x, rb.y, rb.z, rb.w};
#pragma unroll
        for (int i = 0; i < 8; ++i)
#pragma unroll
            for (int j = 0; j < 8; ++j)
                acc[i][j] += rv[i] * fv[j];
    }

#pragma unroll
    for (int i = 0; i < 8; ++i) {
        const size_t row = (size_t)b * 64 + ng * 8 + i;
        float4 o0, o1;
        o0.x = rna_tf32(acc[i][0]); o0.y = rna_tf32(acc[i][1]);
        o0.z = rna_tf32(acc[i][2]); o0.w = rna_tf32(acc[i][3]);
        o1.x = rna_tf32(acc[i][4]); o1.y = rna_tf32(acc[i][5]);
        o1.z = rna_tf32(acc[i][6]); o1.w = rna_tf32(acc[i][7]);
        *(float4*)(agg + row * 1024 + fchunk + fl * 4) = o0;
        *(float4*)(agg + row * 1024 + fchunk + 128 + fl * 4) = o1;
    }
}

// ---------------------------------------------------------------------------
extern "C" void kernel_launch(void* const* d_in, const int* in_sizes, int n_in,
                              void* d_out, int out_size)
{
    const float* feats = (const float*)d_in[0];
    const float* boxes = (const float*)d_in[1];
    const float* Wth   = (const float*)d_in[2];
    const float* bth   = (const float*)d_in[3];
    const float* Wph   = (const float*)d_in[4];
    const float* bph   = (const float*)d_in[5];
    const float* Wg    = (const float*)d_in[6];
    float* out = (float*)d_out;

    float *tp, *agg, *relScratch, *wtp, *wg, *bias;
    cudaGetSymbolAddress((void**)&tp, g_tp);
    cudaGetSymbolAddress((void**)&agg, g_agg);
    cudaGetSymbolAddress((void**)&relScratch, g_rel);
    cudaGetSymbolAddress((void**)&wtp, g_wtp);
    cudaGetSymbolAddress((void**)&wg, g_wg);
    cudaGetSymbolAddress((void**)&bias, g_bias);

    cudaFuncSetAttribute(gemm_tf32<0, 1>,
                         cudaFuncAttributeMaxDynamicSharedMemorySize, GEMM_SMEM);
    cudaFuncSetAttribute(gemm_tf32<1, 0>,
                         cudaFuncAttributeMaxDynamicSharedMemorySize, GEMM_SMEM);
    cudaFuncSetAttribute(agg_kernel,
                         cudaFuncAttributeMaxDynamicSharedMemorySize, AGG_SMEM);

    float* rel = ((size_t)out_size >= OUT_ELEMS + REL_ELEMS)
                     ? out + OUT_ELEMS
                     : relScratch;

    // Launch order keeps gemm1 in the ncu capture slot (4th launch).
    transpose_rna_kernel<<<dim3(8, 32),  dim3(32, 8)>>>(Wth, wtp, 1024, 256);        // 1
    transpose_rna_kernel<<<dim3(8, 32),  dim3(32, 8)>>>(Wph, wtp + (size_t)256 * 1024, 1024, 256); // 2
    bias_concat_kernel<<<1, 512>>>(bth, bph, bias);                                  // 3

    // theta|phi = feats @ [Wth|Wph] + bias   (tf32 mma.sync + ldmatrix)        // 4
    gemm_tf32<0, 1><<<dim3(4, 256), 256, GEMM_SMEM>>>(
        feats, NFG, wtp, NFG, bias, tp, 512, NFG);

    transpose_rna_kernel<<<dim3(32, 32), dim3(32, 8)>>>(Wg, wg, 1024, 1024);         // 5
    // relation_graph (sim + mask + softmax)                                    // 6
    sim_softmax_kernel<<<BB, 256>>>(boxes, rel);
    // agg = relation @ feats (tf32-rounded output)                             // 7
    agg_kernel<<<dim3(BB, 4), 256, AGG_SMEM>>>(feats, rel, agg);
    // out = relu(agg @ Wg)   (tf32 mma.sync + ldmatrix)                        // 8
    gemm_tf32<1, 0><<<dim3(8, 256), 256, GEMM_SMEM>>>(
        agg, NFG, wg, NFG, nullptr, out, NFG, NFG);
}

// round 8
// speedup vs baseline: 1.0362x; 1.0362x over previous
#include <cuda_runtime.h>
#include <math.h>
#include <stdint.h>

// Problem constants (fixed shapes)
#define BB    512
#define NN    64
#define NFG   1024
#define NFR   256
#define MTOT  (BB * NN)                          // 32768
#define OUT_ELEMS  ((size_t)MTOT * NFG)          // 33554432
#define REL_ELEMS  ((size_t)BB * NN * NN)        // 2097152

// Scratch (device globals — allocation-free)
__device__ float g_tp[(size_t)MTOT * 512];       // theta (cols 0..255) | phi (256..511)
__device__ float g_agg[(size_t)MTOT * NFG];      // relation @ feats (tf32-rounded)
__device__ float g_rel[REL_ELEMS];               // fallback relation scratch
__device__ float g_wtp[(size_t)512 * 1024];      // [N=512][K=1024] = [WthT;WphT], tf32-rounded
__device__ float g_wg[(size_t)1024 * 1024];      // WgT [N][K], tf32-rounded
__device__ float g_bias[512];                    // concat(b_theta, b_phi)

// ---------------------------------------------------------------------------
// Helpers (all compute_80-era PTX or older — legal at compute_103)
// ---------------------------------------------------------------------------
__device__ __forceinline__ uint32_t smem_u32(const void* p) {
    uint32_t a;
    asm("{ .reg .u64 t; cvta.to.shared.u64 t, %1; cvt.u32.u64 %0, t; }" : "=r"(a) : "l"(p));
    return a;
}
__device__ __forceinline__ float rna_tf32(float x) {
    uint32_t r;
    asm("cvt.rna.tf32.f32 %0, %1;" : "=r"(r) : "f"(x));
    return __uint_as_float(r);
}
__device__ __forceinline__ void cp_async16(uint32_t dst, const void* src) {
    asm volatile("cp.async.cg.shared.global [%0], [%1], 16;" :: "r"(dst), "l"(src));
}
#define CP_COMMIT() asm volatile("cp.async.commit_group;" ::: "memory")
#define CP_WAIT1()  asm volatile("cp.async.wait_group 1;" ::: "memory")

__device__ __forceinline__ void ldsm_x4(uint32_t& r0, uint32_t& r1,
                                        uint32_t& r2, uint32_t& r3, uint32_t addr) {
    asm volatile("ldmatrix.sync.aligned.m8n8.x4.shared.b16 {%0,%1,%2,%3}, [%4];"
                 : "=r"(r0), "=r"(r1), "=r"(r2), "=r"(r3) : "r"(addr));
}

__device__ __forceinline__ void mma_tf32(float& d0, float& d1, float& d2, float& d3,
                                         uint32_t a0, uint32_t a1, uint32_t a2, uint32_t a3,
                                         uint32_t b0, uint32_t b1) {
    asm volatile(
        "mma.sync.aligned.m16n8k8.row.col.f32.tf32.tf32.f32 "
        "{%0,%1,%2,%3}, {%4,%5,%6,%7}, {%8,%9}, {%0,%1,%2,%3};"
        : "+f"(d0), "+f"(d1), "+f"(d2), "+f"(d3)
        : "r"(a0), "r"(a1), "r"(a2), "r"(a3), "r"(b0), "r"(b1));
}

// ---------------------------------------------------------------------------
// Fused prologue: all weight transposes (+ tf32 rounding) + bias concat
// in ONE launch. Blocks 0..255: Wth; 256..511: Wph; 512..1535: Wg; 1536: bias.
// ---------------------------------------------------------------------------
__global__ void prep_all_kernel(const float* __restrict__ Wth,
                                const float* __restrict__ Wph,
                                const float* __restrict__ Wg,
                                const float* __restrict__ bth,
                                const float* __restrict__ bph,
                                float* __restrict__ wtp,
                                float* __restrict__ wg,
                                float* __restrict__ bias)
{
    __shared__ float tile[32][33];
    const int b = blockIdx.x;
    const int tx = threadIdx.x, ty = threadIdx.y;   // 32 x 8

    if (b >= 1536) {
        int i = ty * 32 + tx;          // 0..255
        bias[i] = bth[i];
        bias[i + 256] = bph[i];
        return;
    }

    const float* src;
    float* dst;
    int K, N, n0, k0;
    if (b < 256) {
        src = Wth; dst = wtp; K = 1024; N = 256;
        n0 = (b & 7) * 32; k0 = (b >> 3) * 32;
    } else if (b < 512) {
        int t = b - 256;
        src = Wph; dst = wtp + (size_t)256 * 1024; K = 1024; N = 256;
        n0 = (t & 7) * 32; k0 = (t >> 3) * 32;
    } else {
        int t = b - 512;
        src = Wg; dst = wg; K = 1024; N = 1024;
        n0 = (t & 31) * 32; k0 = (t >> 5) * 32;
    }
#pragma unroll
    for (int r = 0; r < 32; r += 8)
        tile[ty + r][tx] = src[(size_t)(k0 + ty + r) * N + n0 + tx];
    __syncthreads();
#pragma unroll
    for (int r = 0; r < 32; r += 8)
        dst[(size_t)(n0 + ty + r) * K + k0 + tx] = rna_tf32(tile[tx][ty + r]);
}

// ---------------------------------------------------------------------------
// tf32 mma.sync GEMM with ldmatrix fragments (R6 configuration — best).
// C[M,N] = op(A[M,K] @ Bt[N,K]^T) (+bias) (relu)
// CTA 128x128, BK=32, 3-stage cp.async, 256 threads (8 warps 2x4,
// warp tile 64x32, 4x4 m16n8k8 per k-step), 2 CTAs/SM.
// Bt pre-rounded to tf32; A consumed raw (HMMA truncation, ~6e-5 rel bias).
// ---------------------------------------------------------------------------
#define STAGE_BYTES 32768u                 // A 16KB + B 16KB
#define GEMM_SMEM   (3 * 32768)            // 98304 bytes -> 2 CTAs/SM

template <int RELU, int HASBIAS>
__global__ void __launch_bounds__(256) gemm_tf32(
    const float* __restrict__ A, int lda,
    const float* __restrict__ Bt, int ldb,
    const float* __restrict__ bias,
    float* __restrict__ C, int ldc, int K)
{
    extern __shared__ float sm[];
    const uint32_t smBase = smem_u32(sm);

    const int tid = threadIdx.x;
    const int bm = blockIdx.y * 128;
    const int bn = blockIdx.x * 128;

    const int wid  = tid >> 5;
    const int lane = tid & 31;
    const int g = lane >> 2;                // MMA groupID
    const int t = lane & 3;                 // MMA threadID_in_group
    const int warp_m = (wid & 1) * 64;
    const int warp_n = (wid >> 1) * 32;

    // ldmatrix per-lane row indices (within 128-row tile)
    const int aRow[4] = {
        warp_m + 0 * 16 + (lane & 7) + ((lane >> 3) & 1) * 8,
        warp_m + 1 * 16 + (lane & 7) + ((lane >> 3) & 1) * 8,
        warp_m + 2 * 16 + (lane & 7) + ((lane >> 3) & 1) * 8,
        warp_m + 3 * 16 + (lane & 7) + ((lane >> 3) & 1) * 8 };
    const int aCsel = lane >> 4;            // 0/1 -> k chunk lo/hi
    const int bRow[2] = {
        warp_n + (0 + ((lane >> 4) & 1)) * 8 + (lane & 7),
        warp_n + (2 + ((lane >> 4) & 1)) * 8 + (lane & 7) };
    const int bCsel = (lane >> 3) & 1;

    // stage one BK=32 chunk into buffer s (8 x cp.async 16B per thread)
    auto stage = [&](int kc, int s) {
        const int k0 = kc * 32;
        const uint32_t base = smBase + (uint32_t)s * STAGE_BYTES;
#pragma unroll
        for (int r = 0; r < 4; ++r) {
            int idx = tid + 256 * r;               // 0..1023
            int row = idx >> 3, c = idx & 7;
            uint32_t dst = base + (uint32_t)(row * 128 + ((c ^ (row & 7)) << 4));
            cp_async16(dst, A + (size_t)(bm + row) * lda + k0 + c * 4);
        }
#pragma unroll
        for (int r = 0; r < 4; ++r) {
            int idx = tid + 256 * r;
            int row = idx >> 3, c = idx & 7;
            uint32_t dst = base + 16384u + (uint32_t)(row * 128 + ((c ^ (row & 7)) << 4));
            cp_async16(dst, Bt + (size_t)(bn + row) * ldb + k0 + c * 4);
        }
    };

    float acc[4][4][4];
#pragma unroll
    for (int mt = 0; mt < 4; ++mt)
#pragma unroll
        for (int nt = 0; nt < 4; ++nt)
#pragma unroll
            for (int q = 0; q < 4; ++q) acc[mt][nt][q] = 0.f;

    const int NC = K / 32;
    stage(0, 0); CP_COMMIT();
    stage(1, 1); CP_COMMIT();

    for (int i = 0; i < NC; ++i) {
        CP_WAIT1();               // this thread's copies of chunk i done
        __syncthreads();          // all threads' copies visible; buf (i+2)%3 free
        if (i + 2 < NC) stage(i + 2, (i + 2) % 3);
        CP_COMMIT();

        const uint32_t sb = smBase + (uint32_t)(i % 3) * STAGE_BYTES;
#pragma unroll
        for (int ks = 0; ks < 4; ++ks) {
            uint32_t a[4][4];
#pragma unroll
            for (int mt = 0; mt < 4; ++mt) {
                const int row = aRow[mt];
                const int c = ks * 2 + aCsel;
                ldsm_x4(a[mt][0], a[mt][1], a[mt][2], a[mt][3],
                        sb + (uint32_t)(row * 128 + ((c ^ (row & 7)) << 4)));
            }
            uint32_t b[4][2];
#pragma unroll
            for (int p = 0; p < 2; ++p) {
                const int row = bRow[p];
                const int c = ks * 2 + bCsel;
                ldsm_x4(b[2 * p][0], b[2 * p][1], b[2 * p + 1][0], b[2 * p + 1][1],
                        sb + 16384u + (uint32_t)(row * 128 + ((c ^ (row & 7)) << 4)));
            }
#pragma unroll
            for (int mt = 0; mt < 4; ++mt)
#pragma unroll
                for (int nt = 0; nt < 4; ++nt)
                    mma_tf32(acc[mt][nt][0], acc[mt][nt][1],
                             acc[mt][nt][2], acc[mt][nt][3],
                             a[mt][0], a[mt][1], a[mt][2], a[mt][3],
                             b[nt][0], b[nt][1]);
        }
    }

    // Epilogue: c0,c1 -> (row, col..col+1); c2,c3 -> (row+8, col..col+1)
#pragma unroll
    for (int mt = 0; mt < 4; ++mt) {
        const int row = bm + warp_m + mt * 16 + g;
#pragma unroll
        for (int nt = 0; nt < 4; ++nt) {
            const int col = bn + warp_n + nt * 8 + 2 * t;
            float v0 = acc[mt][nt][0], v1 = acc[mt][nt][1];
            float v2 = acc[mt][nt][2], v3 = acc[mt][nt][3];
            if (HASBIAS) {
                float b0 = bias[col], b1 = bias[col + 1];
                v0 += b0; v1 += b1; v2 += b0; v3 += b1;
            }
            if (RELU) {
                v0 = fmaxf(v0, 0.f); v1 = fmaxf(v1, 0.f);
                v2 = fmaxf(v2, 0.f); v3 = fmaxf(v3, 0.f);
            }
            *(float2*)(C + (size_t)row * ldc + col) = make_float2(v0, v1);
            *(float2*)(C + (size_t)(row + 8) * ldc + col) = make_float2(v2, v3);
        }
    }
}

// ---------------------------------------------------------------------------
// Per-batch: sim = theta @ phi^T / 16, positional mask, softmax over m.
// Softmax parallelized: 8 warps x 8 rows, shfl reductions.
// ---------------------------------------------------------------------------
__global__ void __launch_bounds__(256) sim_softmax_kernel(
    const float* __restrict__ boxes, float* __restrict__ rel)
{
    __shared__ float th_k[32][68];
    __shared__ float ph_k[32][68];
    __shared__ float sS[64 * 65];
    __shared__ float cx[64], cy[64];

    const int b = blockIdx.x;
    const int tid = threadIdx.x;

    if (tid < 64) {
        const float* bb = boxes + ((size_t)b * 64 + tid) * 4;
        cx[tid] = (bb[0] + bb[2]) * 0.5f;
        cy[tid] = (bb[1] + bb[3]) * 0.5f;
    }

    const float4* src4 = (const float4*)(g_tp + (size_t)b * 64 * 512);
    const int tn = (tid >> 4) << 2;
    const int tm = (tid & 15) << 2;

    float acc[4][4];
#pragma unroll
    for (int i = 0; i < 4; ++i)
#pragma unroll
        for (int j = 0; j < 4; ++j) acc[i][j] = 0.f;

    for (int kc = 0; kc < 256; kc += 32) {
        for (int i = tid; i < 512; i += 256) {
            int r = i >> 3;
            int c4 = i & 7;
            int k0 = c4 << 2;
            float4 v = src4[r * 128 + (kc >> 2) + c4];
            th_k[k0 + 0][r] = v.x; th_k[k0 + 1][r] = v.y;
            th_k[k0 + 2][r] = v.z; th_k[k0 + 3][r] = v.w;
            float4 w = src4[r * 128 + 64 + (kc >> 2) + c4];
            ph_k[k0 + 0][r] = w.x; ph_k[k0 + 1][r] = w.y;
            ph_k[k0 + 2][r] = w.z; ph_k[k0 + 3][r] = w.w;
        }
        __syncthreads();
#pragma unroll 8
        for (int k = 0; k < 32; ++k) {
            float a[4], p[4];
#pragma unroll
            for (int i = 0; i < 4; ++i) a[i] = th_k[k][tn + i];
#pragma unroll
            for (int j = 0; j < 4; ++j) p[j] = ph_k[k][tm + j];
#pragma unroll
            for (int i = 0; i < 4; ++i)
#pragma unroll
                for (int j = 0; j < 4; ++j)
                    acc[i][j] += a[i] * p[j];
        }
        __syncthreads();
    }

#pragma unroll
    for (int i = 0; i < 4; ++i)
#pragma unroll
        for (int j = 0; j < 4; ++j)
            sS[(tn + i) * 65 + tm + j] = acc[i][j] * 0.0625f;
    __syncthreads();

    // mask + softmax: warp w handles rows 8w..8w+7; lanes cover m (2 each)
    {
        const int w = tid >> 5;
        const int ln = tid & 31;
        const float thr2 = (0.2f * 157.0f) * (0.2f * 157.0f);
#pragma unroll
        for (int r = 0; r < 8; ++r) {
            const int n = w * 8 + r;
            const float cxn = cx[n], cyn = cy[n];
            float dx0 = cxn - cx[ln], dy0 = cyn - cy[ln];
            float dx1 = cxn - cx[ln + 32], dy1 = cyn - cy[ln + 32];
            float v0 = (dx0 * dx0 + dy0 * dy0 > thr2) ? -INFINITY : sS[n * 65 + ln];
            float v1 = (dx1 * dx1 + dy1 * dy1 > thr2) ? -INFINITY : sS[n * 65 + ln + 32];
            float mx = fmaxf(v0, v1);
#pragma unroll
            for (int o = 16; o; o >>= 1)
                mx = fmaxf(mx, __shfl_xor_sync(0xFFFFFFFFu, mx, o));
            float e0 = expf(v0 - mx);
            float e1 = expf(v1 - mx);
            float s = e0 + e1;
#pragma unroll
            for (int o = 16; o; o >>= 1)
                s += __shfl_xor_sync(0xFFFFFFFFu, s, o);
            const float inv = 1.f / s;
            sS[n * 65 + ln] = e0 * inv;
            sS[n * 65 + ln + 32] = e1 * inv;
        }
    }
    __syncthreads();

    float* ro = rel + (size_t)b * 4096;
    for (int i = tid; i < 4096; i += 256)
        ro[i] = sS[(i >> 6) * 65 + (i & 63)];
}

// ---------------------------------------------------------------------------
// agg = relation[64,64] @ feats[64,1024], output tf32-rounded for GEMM2.
// ---------------------------------------------------------------------------
#define AGG_SMEM ((64 * 256 + 64 * 68) * 4)   // 82944

__global__ void __launch_bounds__(256) agg_kernel(
    const float* __restrict__ feats, const float* __restrict__ rel,
    float* __restrict__ agg)
{
    extern __shared__ float smA[];
    float* sfeats = smA;                 // [64][256]
    float* relT   = smA + 64 * 256;      // [64][68]

    const int b = blockIdx.x;
    const int fchunk = blockIdx.y * 256;
    const int tid = threadIdx.x;

    const float4* fsrc = (const float4*)(feats + (size_t)b * 64 * 1024 + fchunk);
#pragma unroll
    for (int r = 0; r < 16; ++r) {
        int idx = tid + 256 * r;        // 0..4095 float4s
        int m = idx >> 6, c4 = idx & 63;
        *(float4*)(sfeats + m * 256 + c4 * 4) = fsrc[(size_t)m * 256 + c4];
    }
    const float* rsrc = rel + (size_t)b * 4096;
#pragma unroll
    for (int r = 0; r < 16; ++r) {
        int idx = tid + 256 * r;
        int n = idx >> 6, m = idx & 63;
        relT[m * 68 + n] = rsrc[idx];
    }
    __syncthreads();

    const int fl = tid & 31;            // f-cols fl*4..+3 and 128+fl*4..+3
    const int ng = tid >> 5;            // n-rows ng*8..+7

    float acc[8][8];
#pragma unroll
    for (int i = 0; i < 8; ++i)
#pragma unroll
        for (int j = 0; j < 8; ++j) acc[i][j] = 0.f;

    const float* f0p = sfeats + fl * 4;
    const float* f1p = sfeats + 128 + fl * 4;
    const float* rp  = relT + ng * 8;

#pragma unroll 4
    for (int m = 0; m < 64; ++m) {
        float4 fa = *(const float4*)(f0p + m * 256);
        float4 fb = *(const float4*)(f1p + m * 256);
        float4 ra = *(const float4*)(rp + m * 68);
        float4 rb = *(const float4*)(rp + m * 68 + 4);
        float fv[8] = {fa.x, fa.y, fa.z, fa.w, fb.x, fb.y, fb.z, fb.w};
        float rv[8] = {ra.x, ra.y, ra.z, ra.w, rb.x, rb.y, rb.z, rb.w};
#pragma unroll
        for (int i = 0; i < 8; ++i)
#pragma unroll
            for (int j = 0; j < 8; ++j)
                acc[i][j] += rv[i] * fv[j];
    }

#pragma unroll
    for (int i = 0; i < 8; ++i) {
        const size_t row = (size_t)b * 64 + ng * 8 + i;
        float4 o0, o1;
        o0.x = rna_tf32(acc[i][0]); o0.y = rna_tf32(acc[i][1]);
        o0.z = rna_tf32(acc[i][2]); o0.w = rna_tf32(acc[i][3]);
        o1.x = rna_tf32(acc[i][4]); o1.y = rna_tf32(acc[i][5]);
        o1.z = rna_tf32(acc[i][6]); o1.w = rna_tf32(acc[i][7]);
        *(float4*)(agg + row * 1024 + fchunk + fl * 4) = o0;
        *(float4*)(agg + row * 1024 + fchunk + 128 + fl * 4) = o1;
    }
}

// ---------------------------------------------------------------------------
extern "C" void kernel_launch(void* const* d_in, const int* in_sizes, int n_in,
                              void* d_out, int out_size)
{
    const float* feats = (const float*)d_in[0];
    const float* boxes = (const float*)d_in[1];
    const float* Wth   = (const float*)d_in[2];
    const float* bth   = (const float*)d_in[3];
    const float* Wph   = (const float*)d_in[4];
    const float* bph   = (const float*)d_in[5];
    const float* Wg    = (const float*)d_in[6];
    float* out = (float*)d_out;

    float *tp, *agg, *relScratch, *wtp, *wg, *bias;
    cudaGetSymbolAddress((void**)&tp, g_tp);
    cudaGetSymbolAddress((void**)&agg, g_agg);
    cudaGetSymbolAddress((void**)&relScratch, g_rel);
    cudaGetSymbolAddress((void**)&wtp, g_wtp);
    cudaGetSymbolAddress((void**)&wg, g_wg);
    cudaGetSymbolAddress((void**)&bias, g_bias);

    cudaFuncSetAttribute(gemm_tf32<0, 1>,
                         cudaFuncAttributeMaxDynamicSharedMemorySize, GEMM_SMEM);
    cudaFuncSetAttribute(gemm_tf32<1, 0>,
                         cudaFuncAttributeMaxDynamicSharedMemorySize, GEMM_SMEM);
    cudaFuncSetAttribute(agg_kernel,
                         cudaFuncAttributeMaxDynamicSharedMemorySize, AGG_SMEM);

    float* rel = ((size_t)out_size >= OUT_ELEMS + REL_ELEMS)
                     ? out + OUT_ELEMS
                     : relScratch;

    // 5 launches; agg sits in the ncu capture slot (#4).
    prep_all_kernel<<<1537, dim3(32, 8)>>>(Wth, Wph, Wg, bth, bph, wtp, wg, bias); // 1
    gemm_tf32<0, 1><<<dim3(4, 256), 256, GEMM_SMEM>>>(                             // 2
        feats, NFG, wtp, NFG, bias, tp, 512, NFG);
    sim_softmax_kernel<<<BB, 256>>>(boxes, rel);                                   // 3
    agg_kernel<<<dim3(BB, 4), 256, AGG_SMEM>>>(feats, rel, agg);                   // 4
    gemm_tf32<1, 0><<<dim3(8, 256), 256, GEMM_SMEM>>>(                             // 5
        agg, NFG, wg, NFG, nullptr, out, NFG, NFG);
}

// round 9
// speedup vs baseline: 1.1129x; 1.0741x over previous
#include <cuda_runtime.h>
#include <math.h>
#include <stdint.h>

// Problem constants (fixed shapes)
#define BB    512
#define NN    64
#define NFG   1024
#define NFR   256
#define MTOT  (BB * NN)                          // 32768
#define OUT_ELEMS  ((size_t)MTOT * NFG)          // 33554432
#define REL_ELEMS  ((size_t)BB * NN * NN)        // 2097152

// Scratch (device globals — allocation-free)
__device__ float g_tp[(size_t)MTOT * 512];       // theta (cols 0..255) | phi (256..511)
__device__ float g_agg[(size_t)MTOT * NFG];      // relation @ feats (tf32-rounded)
__device__ float g_rel[REL_ELEMS];               // fallback relation scratch
__device__ float g_wtp[(size_t)512 * 1024];      // [N=512][K=1024] = [WthT;WphT], tf32-rounded
__device__ float g_wg[(size_t)1024 * 1024];      // WgT [N][K], tf32-rounded
__device__ float g_bias[512];                    // concat(b_theta, b_phi)

// ---------------------------------------------------------------------------
// Helpers (all compute_80-era PTX or older — legal at compute_103)
// ---------------------------------------------------------------------------
__device__ __forceinline__ uint32_t smem_u32(const void* p) {
    uint32_t a;
    asm("{ .reg .u64 t; cvta.to.shared.u64 t, %1; cvt.u32.u64 %0, t; }" : "=r"(a) : "l"(p));
    return a;
}
__device__ __forceinline__ float rna_tf32(float x) {
    uint32_t r;
    asm("cvt.rna.tf32.f32 %0, %1;" : "=r"(r) : "f"(x));
    return __uint_as_float(r);
}
__device__ __forceinline__ void cp_async16(uint32_t dst, const void* src) {
    asm volatile("cp.async.cg.shared.global [%0], [%1], 16;" :: "r"(dst), "l"(src));
}
#define CP_COMMIT() asm volatile("cp.async.commit_group;" ::: "memory")
#define CP_WAIT1()  asm volatile("cp.async.wait_group 1;" ::: "memory")

__device__ __forceinline__ void ldsm_x4(uint32_t& r0, uint32_t& r1,
                                        uint32_t& r2, uint32_t& r3, uint32_t addr) {
    asm volatile("ldmatrix.sync.aligned.m8n8.x4.shared.b16 {%0,%1,%2,%3}, [%4];"
                 : "=r"(r0), "=r"(r1), "=r"(r2), "=r"(r3) : "r"(addr));
}

__device__ __forceinline__ void mma_tf32(float& d0, float& d1, float& d2, float& d3,
                                         uint32_t a0, uint32_t a1, uint32_t a2, uint32_t a3,
                                         uint32_t b0, uint32_t b1) {
    asm volatile(
        "mma.sync.aligned.m16n8k8.row.col.f32.tf32.tf32.f32 "
        "{%0,%1,%2,%3}, {%4,%5,%6,%7}, {%8,%9}, {%0,%1,%2,%3};"
        : "+f"(d0), "+f"(d1), "+f"(d2), "+f"(d3)
        : "r"(a0), "r"(a1), "r"(a2), "r"(a3), "r"(b0), "r"(b1));
}

// ---------------------------------------------------------------------------
// Fused prologue: all weight transposes (+ tf32 rounding) + bias concat
// in ONE launch. Blocks 0..255: Wth; 256..511: Wph; 512..1535: Wg; 1536: bias.
// ---------------------------------------------------------------------------
__global__ void prep_all_kernel(const float* __restrict__ Wth,
                                const float* __restrict__ Wph,
                                const float* __restrict__ Wg,
                                const float* __restrict__ bth,
                                const float* __restrict__ bph,
                                float* __restrict__ wtp,
                                float* __restrict__ wg,
                                float* __restrict__ bias)
{
    __shared__ float tile[32][33];
    const int b = blockIdx.x;
    const int tx = threadIdx.x, ty = threadIdx.y;   // 32 x 8

    if (b >= 1536) {
        int i = ty * 32 + tx;          // 0..255
        bias[i] = bth[i];
        bias[i + 256] = bph[i];
        return;
    }

    const float* src;
    float* dst;
    int K, N, n0, k0;
    if (b < 256) {
        src = Wth; dst = wtp; K = 1024; N = 256;
        n0 = (b & 7) * 32; k0 = (b >> 3) * 32;
    } else if (b < 512) {
        int t = b - 256;
        src = Wph; dst = wtp + (size_t)256 * 1024; K = 1024; N = 256;
        n0 = (t & 7) * 32; k0 = (t >> 3) * 32;
    } else {
        int t = b - 512;
        src = Wg; dst = wg; K = 1024; N = 1024;
        n0 = (t & 31) * 32; k0 = (t >> 5) * 32;
    }
#pragma unroll
    for (int r = 0; r < 32; r += 8)
        tile[ty + r][tx] = src[(size_t)(k0 + ty + r) * N + n0 + tx];
    __syncthreads();
#pragma unroll
    for (int r = 0; r < 32; r += 8)
        dst[(size_t)(n0 + ty + r) * K + k0 + tx] = rna_tf32(tile[tx][ty + r]);
}

// ---------------------------------------------------------------------------
// tf32 mma.sync GEMM with ldmatrix fragments (R6 configuration — best).
// C[M,N] = op(A[M,K] @ Bt[N,K]^T) (+bias) (relu)
// CTA 128x128, BK=32, 3-stage cp.async, 256 threads (8 warps 2x4,
// warp tile 64x32, 4x4 m16n8k8 per k-step), 2 CTAs/SM.
// Bt pre-rounded to tf32; A consumed raw (HMMA truncation, ~6e-5 rel bias).
// ---------------------------------------------------------------------------
#define STAGE_BYTES 32768u                 // A 16KB + B 16KB
#define GEMM_SMEM   (3 * 32768)            // 98304 bytes -> 2 CTAs/SM

template <int RELU, int HASBIAS>
__global__ void __launch_bounds__(256) gemm_tf32(
    const float* __restrict__ A, int lda,
    const float* __restrict__ Bt, int ldb,
    const float* __restrict__ bias,
    float* __restrict__ C, int ldc, int K)
{
    extern __shared__ float sm[];
    const uint32_t smBase = smem_u32(sm);

    const int tid = threadIdx.x;
    const int bm = blockIdx.y * 128;
    const int bn = blockIdx.x * 128;

    const int wid  = tid >> 5;
    const int lane = tid & 31;
    const int g = lane >> 2;                // MMA groupID
    const int t = lane & 3;                 // MMA threadID_in_group
    const int warp_m = (wid & 1) * 64;
    const int warp_n = (wid >> 1) * 32;

    // ldmatrix per-lane row indices (within 128-row tile)
    const int aRow[4] = {
        warp_m + 0 * 16 + (lane & 7) + ((lane >> 3) & 1) * 8,
        warp_m + 1 * 16 + (lane & 7) + ((lane >> 3) & 1) * 8,
        warp_m + 2 * 16 + (lane & 7) + ((lane >> 3) & 1) * 8,
        warp_m + 3 * 16 + (lane & 7) + ((lane >> 3) & 1) * 8 };
    const int aCsel = lane >> 4;            // 0/1 -> k chunk lo/hi
    const int bRow[2] = {
        warp_n + (0 + ((lane >> 4) & 1)) * 8 + (lane & 7),
        warp_n + (2 + ((lane >> 4) & 1)) * 8 + (lane & 7) };
    const int bCsel = (lane >> 3) & 1;

    // stage one BK=32 chunk into buffer s (8 x cp.async 16B per thread)
    auto stage = [&](int kc, int s) {
        const int k0 = kc * 32;
        const uint32_t base = smBase + (uint32_t)s * STAGE_BYTES;
#pragma unroll
        for (int r = 0; r < 4; ++r) {
            int idx = tid + 256 * r;               // 0..1023
            int row = idx >> 3, c = idx & 7;
            uint32_t dst = base + (uint32_t)(row * 128 + ((c ^ (row & 7)) << 4));
            cp_async16(dst, A + (size_t)(bm + row) * lda + k0 + c * 4);
        }
#pragma unroll
        for (int r = 0; r < 4; ++r) {
            int idx = tid + 256 * r;
            int row = idx >> 3, c = idx & 7;
            uint32_t dst = base + 16384u + (uint32_t)(row * 128 + ((c ^ (row & 7)) << 4));
            cp_async16(dst, Bt + (size_t)(bn + row) * ldb + k0 + c * 4);
        }
    };

    float acc[4][4][4];
#pragma unroll
    for (int mt = 0; mt < 4; ++mt)
#pragma unroll
        for (int nt = 0; nt < 4; ++nt)
#pragma unroll
            for (int q = 0; q < 4; ++q) acc[mt][nt][q] = 0.f;

    const int NC = K / 32;
    stage(0, 0); CP_COMMIT();
    stage(1, 1); CP_COMMIT();

    for (int i = 0; i < NC; ++i) {
        CP_WAIT1();               // this thread's copies of chunk i done
        __syncthreads();          // all threads' copies visible; buf (i+2)%3 free
        if (i + 2 < NC) stage(i + 2, (i + 2) % 3);
        CP_COMMIT();

        const uint32_t sb = smBase + (uint32_t)(i % 3) * STAGE_BYTES;
#pragma unroll
        for (int ks = 0; ks < 4; ++ks) {
            uint32_t a[4][4];
#pragma unroll
            for (int mt = 0; mt < 4; ++mt) {
                const int row = aRow[mt];
                const int c = ks * 2 + aCsel;
                ldsm_x4(a[mt][0], a[mt][1], a[mt][2], a[mt][3],
                        sb + (uint32_t)(row * 128 + ((c ^ (row & 7)) << 4)));
            }
            uint32_t b[4][2];
#pragma unroll
            for (int p = 0; p < 2; ++p) {
                const int row = bRow[p];
                const int c = ks * 2 + bCsel;
                ldsm_x4(b[2 * p][0], b[2 * p][1], b[2 * p + 1][0], b[2 * p + 1][1],
                        sb + 16384u + (uint32_t)(row * 128 + ((c ^ (row & 7)) << 4)));
            }
#pragma unroll
            for (int mt = 0; mt < 4; ++mt)
#pragma unroll
                for (int nt = 0; nt < 4; ++nt)
                    mma_tf32(acc[mt][nt][0], acc[mt][nt][1],
                             acc[mt][nt][2], acc[mt][nt][3],
                             a[mt][0], a[mt][1], a[mt][2], a[mt][3],
                             b[nt][0], b[nt][1]);
        }
    }

    // Epilogue: c0,c1 -> (row, col..col+1); c2,c3 -> (row+8, col..col+1)
#pragma unroll
    for (int mt = 0; mt < 4; ++mt) {
        const int row = bm + warp_m + mt * 16 + g;
#pragma unroll
        for (int nt = 0; nt < 4; ++nt) {
            const int col = bn + warp_n + nt * 8 + 2 * t;
            float v0 = acc[mt][nt][0], v1 = acc[mt][nt][1];
            float v2 = acc[mt][nt][2], v3 = acc[mt][nt][3];
            if (HASBIAS) {
                float b0 = bias[col], b1 = bias[col + 1];
                v0 += b0; v1 += b1; v2 += b0; v3 += b1;
            }
            if (RELU) {
                v0 = fmaxf(v0, 0.f); v1 = fmaxf(v1, 0.f);
                v2 = fmaxf(v2, 0.f); v3 = fmaxf(v3, 0.f);
            }
            *(float2*)(C + (size_t)row * ldc + col) = make_float2(v0, v1);
            *(float2*)(C + (size_t)(row + 8) * ldc + col) = make_float2(v2, v3);
        }
    }
}

// ---------------------------------------------------------------------------
// Per-batch: sim = theta @ phi^T / 16, positional mask, softmax over m.
// Softmax parallelized: 8 warps x 8 rows, shfl reductions.
// rel OUTPUT stays exact fp32 (it is a returned tensor).
// ---------------------------------------------------------------------------
__global__ void __launch_bounds__(256) sim_softmax_kernel(
    const float* __restrict__ boxes, float* __restrict__ rel)
{
    __shared__ float th_k[32][68];
    __shared__ float ph_k[32][68];
    __shared__ float sS[64 * 65];
    __shared__ float cx[64], cy[64];

    const int b = blockIdx.x;
    const int tid = threadIdx.x;

    if (tid < 64) {
        const float* bb = boxes + ((size_t)b * 64 + tid) * 4;
        cx[tid] = (bb[0] + bb[2]) * 0.5f;
        cy[tid] = (bb[1] + bb[3]) * 0.5f;
    }

    const float4* src4 = (const float4*)(g_tp + (size_t)b * 64 * 512);
    const int tn = (tid >> 4) << 2;
    const int tm = (tid & 15) << 2;

    float acc[4][4];
#pragma unroll
    for (int i = 0; i < 4; ++i)
#pragma unroll
        for (int j = 0; j < 4; ++j) acc[i][j] = 0.f;

    for (int kc = 0; kc < 256; kc += 32) {
        for (int i = tid; i < 512; i += 256) {
            int r = i >> 3;
            int c4 = i & 7;
            int k0 = c4 << 2;
            float4 v = src4[r * 128 + (kc >> 2) + c4];
            th_k[k0 + 0][r] = v.x; th_k[k0 + 1][r] = v.y;
            th_k[k0 + 2][r] = v.z; th_k[k0 + 3][r] = v.w;
            float4 w = src4[r * 128 + 64 + (kc >> 2) + c4];
            ph_k[k0 + 0][r] = w.x; ph_k[k0 + 1][r] = w.y;
            ph_k[k0 + 2][r] = w.z; ph_k[k0 + 3][r] = w.w;
        }
        __syncthreads();
#pragma unroll 8
        for (int k = 0; k < 32; ++k) {
            float a[4], p[4];
#pragma unroll
            for (int i = 0; i < 4; ++i) a[i] = th_k[k][tn + i];
#pragma unroll
            for (int j = 0; j < 4; ++j) p[j] = ph_k[k][tm + j];
#pragma unroll
            for (int i = 0; i < 4; ++i)
#pragma unroll
                for (int j = 0; j < 4; ++j)
                    acc[i][j] += a[i] * p[j];
        }
        __syncthreads();
    }

#pragma unroll
    for (int i = 0; i < 4; ++i)
#pragma unroll
        for (int j = 0; j < 4; ++j)
            sS[(tn + i) * 65 + tm + j] = acc[i][j] * 0.0625f;
    __syncthreads();

    // mask + softmax: warp w handles rows 8w..8w+7; lanes cover m (2 each)
    {
        const int w = tid >> 5;
        const int ln = tid & 31;
        const float thr2 = (0.2f * 157.0f) * (0.2f * 157.0f);
#pragma unroll
        for (int r = 0; r < 8; ++r) {
            const int n = w * 8 + r;
            const float cxn = cx[n], cyn = cy[n];
            float dx0 = cxn - cx[ln], dy0 = cyn - cy[ln];
            float dx1 = cxn - cx[ln + 32], dy1 = cyn - cy[ln + 32];
            float v0 = (dx0 * dx0 + dy0 * dy0 > thr2) ? -INFINITY : sS[n * 65 + ln];
            float v1 = (dx1 * dx1 + dy1 * dy1 > thr2) ? -INFINITY : sS[n * 65 + ln + 32];
            float mx = fmaxf(v0, v1);
#pragma unroll
            for (int o = 16; o; o >>= 1)
                mx = fmaxf(mx, __shfl_xor_sync(0xFFFFFFFFu, mx, o));
            float e0 = expf(v0 - mx);
            float e1 = expf(v1 - mx);
            float s = e0 + e1;
#pragma unroll
            for (int o = 16; o; o >>= 1)
                s += __shfl_xor_sync(0xFFFFFFFFu, s, o);
            const float inv = 1.f / s;
            sS[n * 65 + ln] = e0 * inv;
            sS[n * 65 + ln + 32] = e1 * inv;
        }
    }
    __syncthreads();

    float* ro = rel + (size_t)b * 4096;
    for (int i = tid; i < 4096; i += 256)
        ro[i] = sS[(i >> 6) * 65 + (i & 63)];
}

// ---------------------------------------------------------------------------
// agg = relation[64,64] @ feats[64,1024] via tf32 mma.sync.
// CTA = (batch, 256-col chunk), 256 threads = 8 warps, warp tile 64x32, K=64.
// A = rel (row-major [n][m] = [M][K]) staged RNA into srel[64][68].
// B = feats columns: staged RNA into sfeats[64][264] ([m][f], padded);
// fragments via plain LDS.32 (bank-exact: A 4g+t, B 8t+g — all distinct).
// Output tf32-rounded for gemm2. rel output unaffected.
// ---------------------------------------------------------------------------
#define AGG_SMEM ((64 * 264 + 64 * 68) * 4)   // 84992

__global__ void __launch_bounds__(256) agg_kernel(
    const float* __restrict__ feats, const float* __restrict__ rel,
    float* __restrict__ agg)
{
    extern __shared__ float smA[];
    float* sfeats = smA;                 // [64][264]  ([m][f])
    float* srel   = smA + 64 * 264;      // [64][68]   ([n][m])

    const int b = blockIdx.x;
    const int fchunk = blockIdx.y * 256;
    const int tid = threadIdx.x;

    // stage feats (RNA-rounded to tf32)
    const float4* fsrc = (const float4*)(feats + (size_t)b * 64 * 1024 + fchunk);
#pragma unroll
    for (int r = 0; r < 16; ++r) {
        int idx = tid + 256 * r;        // 0..4095 float4s
        int m = idx >> 6, c4 = idx & 63;
        float4 v = fsrc[(size_t)m * 256 + c4];
        v.x = rna_tf32(v.x); v.y = rna_tf32(v.y);
        v.z = rna_tf32(v.z); v.w = rna_tf32(v.w);
        *(float4*)(sfeats + m * 264 + c4 * 4) = v;
    }
    // stage rel (RNA-rounded to tf32)
    const float4* rsrc = (const float4*)(rel + (size_t)b * 4096);
#pragma unroll
    for (int r = 0; r < 4; ++r) {
        int idx = tid + 256 * r;        // 0..1023 float4s
        int n = idx >> 4, c4 = idx & 15;
        float4 v = rsrc[idx];
        v.x = rna_tf32(v.x); v.y = rna_tf32(v.y);
        v.z = rna_tf32(v.z); v.w = rna_tf32(v.w);
        *(float4*)(srel + n * 68 + c4 * 4) = v;
    }
    __syncthreads();

    const int wid  = tid >> 5;
    const int lane = tid & 31;
    const int g = lane >> 2;
    const int t = lane & 3;
    const int warp_n = wid * 32;         // f-offset within 256 chunk

    float acc[4][4][4];
#pragma unroll
    for (int mt = 0; mt < 4; ++mt)
#pragma unroll
        for (int nt = 0; nt < 4; ++nt)
#pragma unroll
            for (int q = 0; q < 4; ++q) acc[mt][nt][q] = 0.f;

#pragma unroll
    for (int ks = 0; ks < 8; ++ks) {
        const int k0 = ks * 8;
        uint32_t a[4][4];
#pragma unroll
        for (int mt = 0; mt < 4; ++mt) {
            a[mt][0] = __float_as_uint(srel[(mt * 16 + g) * 68 + k0 + t]);
            a[mt][1] = __float_as_uint(srel[(mt * 16 + 8 + g) * 68 + k0 + t]);
            a[mt][2] = __float_as_uint(srel[(mt * 16 + g) * 68 + k0 + 4 + t]);
            a[mt][3] = __float_as_uint(srel[(mt * 16 + 8 + g) * 68 + k0 + 4 + t]);
        }
        uint32_t bf[4][2];
#pragma unroll
        for (int nt = 0; nt < 4; ++nt) {
            bf[nt][0] = __float_as_uint(sfeats[(k0 + t) * 264 + warp_n + nt * 8 + g]);
            bf[nt][1] = __float_as_uint(sfeats[(k0 + 4 + t) * 264 + warp_n + nt * 8 + g]);
        }
#pragma unroll
        for (int mt = 0; mt < 4; ++mt)
#pragma unroll
            for (int nt = 0; nt < 4; ++nt)
                mma_tf32(acc[mt][nt][0], acc[mt][nt][1],
                         acc[mt][nt][2], acc[mt][nt][3],
                         a[mt][0], a[mt][1], a[mt][2], a[mt][3],
                         bf[nt][0], bf[nt][1]);
    }

    // Epilogue: RNA-round for gemm2 consumption
#pragma unroll
    for (int mt = 0; mt < 4; ++mt) {
        const size_t row0 = (size_t)b * 64 + mt * 16 + g;
#pragma unroll
        for (int nt = 0; nt < 4; ++nt) {
            const int col = fchunk + warp_n + nt * 8 + 2 * t;
            float2 p0 = make_float2(rna_tf32(acc[mt][nt][0]), rna_tf32(acc[mt][nt][1]));
            float2 p1 = make_float2(rna_tf32(acc[mt][nt][2]), rna_tf32(acc[mt][nt][3]));
            *(float2*)(agg + row0 * 1024 + col) = p0;
            *(float2*)(agg + (row0 + 8) * 1024 + col) = p1;
        }
    }
}

// ---------------------------------------------------------------------------
extern "C" void kernel_launch(void* const* d_in, const int* in_sizes, int n_in,
                              void* d_out, int out_size)
{
    const float* feats = (const float*)d_in[0];
    const float* boxes = (const float*)d_in[1];
    const float* Wth   = (const float*)d_in[2];
    const float* bth   = (const float*)d_in[3];
    const float* Wph   = (const float*)d_in[4];
    const float* bph   = (const float*)d_in[5];
    const float* Wg    = (const float*)d_in[6];
    float* out = (float*)d_out;

    float *tp, *agg, *relScratch, *wtp, *wg, *bias;
    cudaGetSymbolAddress((void**)&tp, g_tp);
    cudaGetSymbolAddress((void**)&agg, g_agg);
    cudaGetSymbolAddress((void**)&relScratch, g_rel);
    cudaGetSymbolAddress((void**)&wtp, g_wtp);
    cudaGetSymbolAddress((void**)&wg, g_wg);
    cudaGetSymbolAddress((void**)&bias, g_bias);

    cudaFuncSetAttribute(gemm_tf32<0, 1>,
                         cudaFuncAttributeMaxDynamicSharedMemorySize, GEMM_SMEM);
    cudaFuncSetAttribute(gemm_tf32<1, 0>,
                         cudaFuncAttributeMaxDynamicSharedMemorySize, GEMM_SMEM);
    cudaFuncSetAttribute(agg_kernel,
                         cudaFuncAttributeMaxDynamicSharedMemorySize, AGG_SMEM);

    float* rel = ((size_t)out_size >= OUT_ELEMS + REL_ELEMS)
                     ? out + OUT_ELEMS
                     : relScratch;

    // 5 launches; agg sits in the ncu capture slot (#4).
    prep_all_kernel<<<1537, dim3(32, 8)>>>(Wth, Wph, Wg, bth, bph, wtp, wg, bias); // 1
    gemm_tf32<0, 1><<<dim3(4, 256), 256, GEMM_SMEM>>>(                             // 2
        feats, NFG, wtp, NFG, bias, tp, 512, NFG);
    sim_softmax_kernel<<<BB, 256>>>(boxes, rel);                                   // 3
    agg_kernel<<<dim3(BB, 4), 256, AGG_SMEM>>>(feats, rel, agg);                   // 4
    gemm_tf32<1, 0><<<dim3(8, 256), 256, GEMM_SMEM>>>(                             // 5
        agg, NFG, wg, NFG, nullptr, out, NFG, NFG);
}